// round 1
// baseline (speedup 1.0000x reference)
#include <cuda_runtime.h>
#include <cstdint>

// out[n, d] = x[n, d] * w[d];  N = DIM = 8192, fp32.
// Pure HBM-streaming kernel: 128-bit vectorized grid-stride loop.
// w (32 KB) becomes L1-resident; x/out stream at DRAM bandwidth.

static constexpr int DIM = 8192;
static constexpr int DIM4 = DIM / 4;          // 2048 float4 per row

__global__ void __launch_bounds__(256)
diag_scale_kernel(const float4* __restrict__ x,
                  const float4* __restrict__ w4,
                  float4* __restrict__ out,
                  long long n4)
{
    long long i = (long long)blockIdx.x * blockDim.x + threadIdx.x;
    long long stride = (long long)gridDim.x * blockDim.x;

    for (; i < n4; i += stride) {
        float4 v = x[i];
        // column (in float4 units) within the row; DIM4 is a power of two
        int col4 = (int)(i & (long long)(DIM4 - 1));
        float4 wv = __ldg(&w4[col4]);
        v.x *= wv.x;
        v.y *= wv.y;
        v.z *= wv.z;
        v.w *= wv.w;
        out[i] = v;
    }
}

extern "C" void kernel_launch(void* const* d_in, const int* in_sizes, int n_in,
                              void* d_out, int out_size)
{
    const float4* x  = (const float4*)d_in[0];   // x: [N, DIM] fp32
    const float4* w4 = (const float4*)d_in[1];   // diagonal_weights: [DIM] fp32
    float4* out = (float4*)d_out;

    long long n4 = (long long)out_size / 4;      // total float4 elements

    const int threads = 256;
    // ~4 waves of 256-thread blocks across 148+ SMs; grid-stride covers the rest
    int blocks = 148 * 8 * 4;                    // 4736 blocks
    long long needed = (n4 + threads - 1) / threads;
    if ((long long)blocks > needed) blocks = (int)needed;

    diag_scale_kernel<<<blocks, threads>>>(x, w4, out, n4);
}